// round 5
// baseline (speedup 1.0000x reference)
#include <cuda_runtime.h>
#include <math.h>

#define BB   1024
#define NN   40
#define ETAD 64
#define KK   32
#define ZDIM 32
#define NA   10
#define NB   5
#define CH   128
#define AH   128
#define BH   64
#define NODES (BB*NN)        /* 40960 */
#define EPB   780            /* C(40,2) edges per batch */
#define ZPAD  36             /* padded row stride (floats), 16B aligned, LDS.128 conflict-free */

/* ---- scratch (static device memory; allocation-free).
   __align__(16): accessed through float4 casts. ---- */
__device__ __align__(16) float g_s[BB*KK];           /* pre-softmax cluster logits */
__device__ __align__(16) float g_z[NODES*ZDIM];      /* latent z per node          */
__device__ __align__(16) float g_wsym[NB*ZDIM*ZDIM]; /* symmetrized bond matrices  */

/* ---- f32x2 packed helpers (sm_100+) ---- */
__device__ __forceinline__ unsigned long long pk2(float lo, float hi) {
    unsigned long long r;
    asm("mov.b64 %0, {%1, %2};" : "=l"(r) : "f"(lo), "f"(hi));
    return r;
}
__device__ __forceinline__ void upk2(unsigned long long v, float& lo, float& hi) {
    asm("mov.b64 {%0, %1}, %2;" : "=f"(lo), "=f"(hi) : "l"(v));
}
__device__ __forceinline__ unsigned long long fma2(unsigned long long a,
                                                   unsigned long long b,
                                                   unsigned long long c) {
    unsigned long long r;
    asm("fma.rn.f32x2 %0, %1, %2, %3;" : "=l"(r) : "l"(a), "l"(b), "l"(c));
    return r;
}

/* lex-order edge index for pair (i<j) within a batch of NN nodes */
__device__ __forceinline__ int eidx(int i, int j) {
    return i*(2*NN - 1 - i)/2 + (j - i - 1);
}

/* ---------------- kernel 0: Wsym = 0.5*(W + W^T) ---------------- */
__global__ void k_wsym(const float* __restrict__ bm) {
    int i = blockIdx.x * blockDim.x + threadIdx.x;
    if (i < NB*ZDIM*ZDIM) {
        int t = i / (ZDIM*ZDIM);
        int r = (i / ZDIM) % ZDIM;
        int c = i % ZDIM;
        g_wsym[i] = 0.5f * (bm[t*ZDIM*ZDIM + r*ZDIM + c] +
                            bm[t*ZDIM*ZDIM + c*ZDIM + r]);
    }
}

/* -------- kernel 1: per-batch cluster resblock logits s[b,k] -------- */
__global__ void k_cluster(const float* __restrict__ eta,
                          const float* __restrict__ cW1, const float* __restrict__ cb1,
                          const float* __restrict__ cW2, const float* __restrict__ cb2,
                          const float* __restrict__ cWs, const float* __restrict__ cbs) {
    __shared__ float eta_sm[ETAD];
    __shared__ float h_sm[CH];
    int b = blockIdx.x;
    int t = threadIdx.x;           /* 128 threads */
    if (t < ETAD) eta_sm[t] = eta[b*ETAD + t];
    __syncthreads();
    float acc = cb1[t];
    #pragma unroll 16
    for (int e = 0; e < ETAD; e++) acc = fmaf(eta_sm[e], cW1[e*CH + t], acc);
    h_sm[t] = fmaxf(acc, 0.f);
    __syncthreads();
    if (t < KK) {
        float s = cb2[t] + cbs[t];
        #pragma unroll 16
        for (int j = 0; j < CH; j++) s = fmaf(h_sm[j], cW2[j*KK + t], s);
        #pragma unroll 16
        for (int e = 0; e < ETAD; e++) s = fmaf(eta_sm[e], cWs[e*KK + t], s);
        g_s[b*KK + t] = s;
    }
}

/* -------- kernel 2: warp-per-node x4: argmax -> z -> atom MLP -------- */
__global__ __launch_bounds__(256)
void k_node(const float* __restrict__ gum, const float* __restrict__ zn,
            const float* __restrict__ cm,  const float* __restrict__ cls,
            const float* __restrict__ aW1, const float* __restrict__ ab1,
            const float* __restrict__ aW2, const float* __restrict__ ab2,
            const float* __restrict__ aWs, const float* __restrict__ absk,
            float* __restrict__ atom_out) {
    __shared__ float4 w1s4[ZDIM*32];   /* aW1, [d][lane] float4 units: 16KB */
    __shared__ float  aw2s[AH*NA];     /* [j][o] 5KB   */
    __shared__ float  awss[ZDIM*NA];   /* [d][o] 1.25KB */
    __shared__ float4 ab1s4[32];
    __shared__ float  ab2s[NA];        /* ab2 + abs_   */
    __shared__ __align__(16) float  zsm[8][ZDIM];
    __shared__ __align__(16) float  hsm[8][AH];

    int tid  = threadIdx.x;
    int warp = tid >> 5;
    int lane = tid & 31;

    for (int i = tid; i < ZDIM*32; i += 256) w1s4[i] = ((const float4*)aW1)[i];
    for (int i = tid; i < AH*NA;  i += 256) aw2s[i]  = aW2[i];
    for (int i = tid; i < ZDIM*NA; i += 256) awss[i] = aWs[i];
    if (tid < 32) ab1s4[tid] = ((const float4*)ab1)[tid];
    if (tid < NA) ab2s[tid]  = ab2[tid] + absk[tid];
    __syncthreads();

    int node0 = blockIdx.x * 32 + warp;

    #pragma unroll
    for (int u = 0; u < 4; u++) {
        int node = node0 + u*8;
        int b = node / NN;

        float val = g_s[b*KK + lane] + gum[node*KK + lane];
        int idx = lane;
        #pragma unroll
        for (int off = 16; off; off >>= 1) {
            float ov = __shfl_xor_sync(0xffffffffu, val, off);
            int   oi = __shfl_xor_sync(0xffffffffu, idx, off);
            if (ov > val || (ov == val && oi < idx)) { val = ov; idx = oi; }
        }
        int kmax = idx;

        float ls = cls[kmax*ZDIM + lane];
        float sg = __expf(fminf(fmaxf(ls, -20.f), 30.f));
        float z  = fmaf(zn[node*ZDIM + lane], sg, cm[kmax*ZDIM + lane]);
        g_z[node*ZDIM + lane] = z;
        zsm[warp][lane] = z;
        __syncwarp();

        float4 acc = ab1s4[lane];
        #pragma unroll
        for (int d = 0; d < ZDIM; d++) {
            float zd = zsm[warp][d];
            float4 w = w1s4[d*32 + lane];
            acc.x = fmaf(zd, w.x, acc.x);
            acc.y = fmaf(zd, w.y, acc.y);
            acc.z = fmaf(zd, w.z, acc.z);
            acc.w = fmaf(zd, w.w, acc.w);
        }
        acc.x = fmaxf(acc.x, 0.f); acc.y = fmaxf(acc.y, 0.f);
        acc.z = fmaxf(acc.z, 0.f); acc.w = fmaxf(acc.w, 0.f);
        reinterpret_cast<float4*>(hsm[warp])[lane] = acc;
        __syncwarp();

        if (lane < NA) {
            float o = ab2s[lane];
            #pragma unroll 8
            for (int j = 0; j < AH; j++) o = fmaf(hsm[warp][j], aw2s[j*NA + lane], o);
            #pragma unroll
            for (int d = 0; d < ZDIM; d++) o = fmaf(zsm[warp][d], awss[d*NA + lane], o);
            atom_out[node*NA + lane] = o;
        }
        __syncwarp();
    }
}

/* -------- kernel 3: block-per-batch edge pipeline, 2x2 node tiles -------- */
/* Edge list is lex-order combinations(range(40),2) (fixed by the reference  */
/* setup), so edge indices are computed analytically; edge_index unused.     */
__global__ __launch_bounds__(256)
void k_edge(const float* __restrict__ bW1, const float* __restrict__ bb1,
            const float* __restrict__ bW2, const float* __restrict__ bb2,
            const float* __restrict__ bWs, const float* __restrict__ bbs,
            float* __restrict__ edge_out) {
    __shared__ __align__(16) float zs[NN*ZPAD];        /* z[j][d], padded        */
    __shared__ __align__(16) float vs[NB*NN*ZPAD];     /* v[t][j][d], padded     */
    __shared__ __align__(16) float w1s[NB*BH];         /* [t][j]                 */
    __shared__ __align__(16) float w2t[NB*BH];         /* transposed to [t][j]   */
    __shared__ __align__(16) float b1s[BH];
    __shared__ float wss_s[NB*NB];                     /* [u][t]                 */
    __shared__ float b2s[NB];                          /* b2 + bbs               */

    int b   = blockIdx.x;
    int tid = threadIdx.x;

    /* ---- stage weights ---- */
    for (int i = tid; i < NB*BH; i += 256) {
        w1s[i] = bW1[i];
        int t = i >> 6, j = i & 63;
        w2t[i] = bW2[j*NB + t];
    }
    if (tid < NB*NB) wss_s[tid] = bWs[tid];
    if (tid < BH)    b1s[tid]   = bb1[tid];
    if (tid < NB)    b2s[tid]   = bb2[tid] + bbs[tid];

    /* ---- stage z (vectorized, padded) ---- */
    for (int i = tid; i < NN*8; i += 256) {            /* 320 float4s */
        int n = i >> 3, d4 = i & 7;
        *reinterpret_cast<float4*>(&zs[n*ZPAD + d4*4]) =
            reinterpret_cast<const float4*>(g_z)[(size_t)b*NN*8 + i];
    }
    __syncthreads();

    /* ---- v[t][j][d] = sum_c Wsym[t][c][d] * z[j][c] ---- */
    for (int base = 0; base < NN*8; base += 256) {
        int idx = base + tid;
        if (idx < NN*8) {
            int j = idx >> 3, d4 = idx & 7;
            #pragma unroll
            for (int t = 0; t < NB; t++) {
                float4 acc = make_float4(0.f, 0.f, 0.f, 0.f);
                const float4* W = reinterpret_cast<const float4*>(g_wsym) + t*256 + d4;
                #pragma unroll 8
                for (int c = 0; c < ZDIM; c++) {
                    float zc = zs[j*ZPAD + c];
                    float4 w = W[c*8];
                    acc.x = fmaf(zc, w.x, acc.x);
                    acc.y = fmaf(zc, w.y, acc.y);
                    acc.z = fmaf(zc, w.z, acc.z);
                    acc.w = fmaf(zc, w.w, acc.w);
                }
                *reinterpret_cast<float4*>(&vs[t*NN*ZPAD + j*ZPAD + d4*4]) = acc;
            }
        }
    }
    __syncthreads();

    /* ---- 2x2 node tiles: threads 0..189 = off-diag tiles (4 edges each),
            threads 190..209 = diagonal singleton edges (2I, 2I+1).       ---- */
    if (tid < 210) {
        int i0, i1, j0, j1;
        if (tid < 190) {
            int q = tid, I = 0;
            while (q >= 19 - I) { q -= 19 - I; I++; }
            int J = I + 1 + q;
            i0 = 2*I; i1 = 2*I + 1; j0 = 2*J; j1 = 2*J + 1;
        } else {
            int I = tid - 190;
            i0 = 2*I; i1 = 2*I; j0 = 2*I + 1; j1 = 2*I + 1;  /* degenerate: 4 identical edges */
        }

        int ee[4] = { eidx(i0, j0), eidx(i0, j1), eidx(i1, j0), eidx(i1, j1) };

        /* ---- bilinear for 4 edges with shared z/v loads ---- */
        float bil[4][NB];
        #pragma unroll
        for (int e = 0; e < 4; e++)
            #pragma unroll
            for (int t = 0; t < NB; t++) bil[e][t] = 0.f;

        #pragma unroll
        for (int d4 = 0; d4 < 8; d4++) {
            float4 z0 = *reinterpret_cast<const float4*>(&zs[i0*ZPAD + d4*4]);
            float4 z1 = *reinterpret_cast<const float4*>(&zs[i1*ZPAD + d4*4]);
            #pragma unroll
            for (int t = 0; t < NB; t++) {
                float4 va = *reinterpret_cast<const float4*>(&vs[t*NN*ZPAD + j0*ZPAD + d4*4]);
                float4 vb = *reinterpret_cast<const float4*>(&vs[t*NN*ZPAD + j1*ZPAD + d4*4]);
                bil[0][t] = fmaf(z0.x, va.x, fmaf(z0.y, va.y, fmaf(z0.z, va.z, fmaf(z0.w, va.w, bil[0][t]))));
                bil[1][t] = fmaf(z0.x, vb.x, fmaf(z0.y, vb.y, fmaf(z0.z, vb.z, fmaf(z0.w, vb.w, bil[1][t]))));
                bil[2][t] = fmaf(z1.x, va.x, fmaf(z1.y, va.y, fmaf(z1.z, va.z, fmaf(z1.w, va.w, bil[2][t]))));
                bil[3][t] = fmaf(z1.x, vb.x, fmaf(z1.y, vb.y, fmaf(z1.z, vb.z, fmaf(z1.w, vb.w, bil[3][t]))));
            }
        }

        /* ---- skip path + packed setup ---- */
        unsigned long long oo[4][NB], bp[4][NB];
        #pragma unroll
        for (int e = 0; e < 4; e++) {
            #pragma unroll
            for (int t = 0; t < NB; t++) {
                float s = b2s[t];
                #pragma unroll
                for (int u = 0; u < NB; u++) s = fmaf(bil[e][u], wss_s[u*NB + t], s);
                oo[e][t] = pk2(s, 0.f);
                bp[e][t] = pk2(bil[e][t], bil[e][t]);
            }
        }

        /* ---- hidden layer: 32 j-pairs, weights amortized over 4 edges ---- */
        #pragma unroll 2
        for (int jp = 0; jp < BH/2; jp++) {
            unsigned long long b1p = *reinterpret_cast<const unsigned long long*>(&b1s[2*jp]);
            unsigned long long h[4] = { b1p, b1p, b1p, b1p };
            #pragma unroll
            for (int t = 0; t < NB; t++) {
                unsigned long long w1p =
                    *reinterpret_cast<const unsigned long long*>(&w1s[t*BH + 2*jp]);
                #pragma unroll
                for (int e = 0; e < 4; e++) h[e] = fma2(bp[e][t], w1p, h[e]);
            }
            #pragma unroll
            for (int e = 0; e < 4; e++) {
                float x, y; upk2(h[e], x, y);
                h[e] = pk2(fmaxf(x, 0.f), fmaxf(y, 0.f));
            }
            #pragma unroll
            for (int t = 0; t < NB; t++) {
                unsigned long long w2p =
                    *reinterpret_cast<const unsigned long long*>(&w2t[t*BH + 2*jp]);
                #pragma unroll
                for (int e = 0; e < 4; e++) oo[e][t] = fma2(h[e], w2p, oo[e][t]);
            }
        }

        /* ---- reduce halves, softmax, store (diag: 4 identical stores) ---- */
        float* outb = edge_out + (size_t)b * EPB * NB;
        #pragma unroll
        for (int e = 0; e < 4; e++) {
            float o[NB];
            #pragma unroll
            for (int t = 0; t < NB; t++) {
                float x, y; upk2(oo[e][t], x, y); o[t] = x + y;
            }
            float m = o[0];
            #pragma unroll
            for (int t = 1; t < NB; t++) m = fmaxf(m, o[t]);
            float s = 0.f, ex[NB];
            #pragma unroll
            for (int t = 0; t < NB; t++) { ex[t] = __expf(o[t] - m); s += ex[t]; }
            float inv = __fdividef(1.f, s);
            #pragma unroll
            for (int t = 0; t < NB; t++) outb[ee[e]*NB + t] = ex[t] * inv;
        }
    }
}

/* ------------------------- launch ------------------------- */
extern "C" void kernel_launch(void* const* d_in, const int* in_sizes, int n_in,
                              void* d_out, int out_size) {
    const float* eta  = (const float*)d_in[0];
    const float* gum  = (const float*)d_in[1];
    const float* zn   = (const float*)d_in[2];
    const float* cW1  = (const float*)d_in[3];
    const float* cb1  = (const float*)d_in[4];
    const float* cW2  = (const float*)d_in[5];
    const float* cb2  = (const float*)d_in[6];
    const float* cWs  = (const float*)d_in[7];
    const float* cbs  = (const float*)d_in[8];
    const float* cm   = (const float*)d_in[9];
    const float* cls  = (const float*)d_in[10];
    const float* aW1  = (const float*)d_in[11];
    const float* ab1  = (const float*)d_in[12];
    const float* aW2  = (const float*)d_in[13];
    const float* ab2  = (const float*)d_in[14];
    const float* aWs  = (const float*)d_in[15];
    const float* absk = (const float*)d_in[16];
    const float* bm   = (const float*)d_in[17];
    const float* bW1  = (const float*)d_in[18];
    const float* bb1  = (const float*)d_in[19];
    const float* bW2  = (const float*)d_in[20];
    const float* bb2  = (const float*)d_in[21];
    const float* bWs  = (const float*)d_in[22];
    const float* bbs  = (const float*)d_in[23];

    float* atom_out = (float*)d_out;                 /* [40960,10]  */
    float* edge_out = atom_out + (size_t)NODES * NA; /* [798720,5]  */

    k_wsym   <<<(NB*ZDIM*ZDIM + 255)/256, 256>>>(bm);
    k_cluster<<<BB, CH>>>(eta, cW1, cb1, cW2, cb2, cWs, cbs);
    k_node   <<<NODES/32, 256>>>(gum, zn, cm, cls, aW1, ab1, aW2, ab2, aWs, absk, atom_out);
    k_edge   <<<BB, 256>>>(bW1, bb1, bW2, bb2, bWs, bbs, edge_out);
}